// round 8
// baseline (speedup 1.0000x reference)
#include <cuda_runtime.h>
#include <cuda_fp16.h>
#include <cstdint>

#define BB 16
#define TT 2048
#define DD 1024
#define HH 128
#define BT (BB*TT)

// ---------------- device scratch (allocation-free rule) ----------------
__device__ __align__(128) __half g_xh[(size_t)BT*DD];      // half copy of x
__device__ __align__(128) __half g_qh[(size_t)BT*HH];      // half, pre-scaled
__device__ __align__(128) __half g_kh[(size_t)BT*HH];
__device__ __align__(128) float  g_v [(size_t)BT*HH];      // fp32 (scaled later)
__device__ __align__(128) __half g_Wth[3*(size_t)HH*DD];   // [sel][n][k]
__device__ __align__(128) __half g_Vth[(size_t)BB*HH*TT];  // [b][h][k] = v/colsum
__device__ __align__(128) float  g_colsum[BT];
__device__ __align__(128) __half g_Eh[(size_t)BB*TT*TT];   // exp(masked S)

// ---------------- helpers ----------------
__device__ __forceinline__ uint32_t smem_u32(const void* p) {
    uint32_t a;
    asm("{ .reg .u64 t; cvta.to.shared.u64 t, %1; cvt.u32.u64 %0, t; }" : "=r"(a) : "l"(p));
    return a;
}
__device__ __forceinline__ void ldsm4(uint32_t& r0, uint32_t& r1, uint32_t& r2, uint32_t& r3,
                                      uint32_t addr) {
    asm volatile("ldmatrix.sync.aligned.m8n8.x4.shared.b16 {%0,%1,%2,%3}, [%4];"
                 : "=r"(r0), "=r"(r1), "=r"(r2), "=r"(r3) : "r"(addr));
}
__device__ __forceinline__ void mma16(float* c, const uint32_t* a, const uint32_t* b) {
    asm volatile(
        "mma.sync.aligned.m16n8k16.row.col.f32.f16.f16.f32 "
        "{%0,%1,%2,%3}, {%4,%5,%6,%7}, {%8,%9}, {%0,%1,%2,%3};"
        : "+f"(c[0]), "+f"(c[1]), "+f"(c[2]), "+f"(c[3])
        : "r"(a[0]), "r"(a[1]), "r"(a[2]), "r"(a[3]), "r"(b[0]), "r"(b[1]));
}

#define BK 64                    // k-slab (halves)
#define PH 72                    // halves per smem row (144B): ldmatrix conflict-free
#define NSTAGE 3
// block tiles: (MR=256,NR=128) or (MR=128,NR=256) -> same stage size
#define STAGEB ((256 + 128) * PH * 2)        // 55296 B
#define GEMM_SMEM (NSTAGE * STAGEB)          // 165888 B

// cp.async 16B stage of a ROWSx64-half chunk (row stride ld halves), 256 threads
template<int ROWS>
__device__ __forceinline__ void stage_cp(uint32_t s, const __half* __restrict__ g,
                                         size_t ld, int tid) {
    #pragma unroll
    for (int i = 0; i < ROWS / 32; i++) {
        int idx = tid + i * 256;
        int r = idx >> 3, c8 = idx & 7;
        uint32_t dst = s + (uint32_t)(r * PH + c8 * 8) * 2u;
        const __half* src = g + (size_t)r * ld + c8 * 8;
        asm volatile("cp.async.cg.shared.global [%0], [%1], 16;" :: "r"(dst), "l"(src));
    }
}
#define CP_COMMIT() asm volatile("cp.async.commit_group;" ::: "memory")

// warp tile 64(M) x 64(N). One BK=64 slab = four k16 steps.
__device__ __forceinline__ void compute_tile(uint32_t sA, uint32_t sB,
                                             uint32_t aoff, uint32_t boff,
                                             float c[4][8][4]) {
    #pragma unroll
    for (int ks = 0; ks < 4; ks++) {
        uint32_t a[4][4], b[8][2];
        #pragma unroll
        for (int mt = 0; mt < 4; mt++)
            ldsm4(a[mt][0], a[mt][1], a[mt][2], a[mt][3],
                  sA + aoff + mt * (16 * PH * 2) + ks * 32);
        #pragma unroll
        for (int np = 0; np < 4; np++)
            ldsm4(b[2*np][0], b[2*np][1], b[2*np+1][0], b[2*np+1][1],
                  sB + boff + np * (16 * PH * 2) + ks * 32);
        #pragma unroll
        for (int mt = 0; mt < 4; mt++)
            #pragma unroll
            for (int nt = 0; nt < 8; nt++)
                mma16(c[mt][nt], a[mt], b[nt]);
    }
}

// block GEMM: C[MRxNR] = A[MRxK] * B[NRxK]^T, 256 threads, 3 cp.async stages
template<int MR, int NR>
__device__ __forceinline__ void gemm_main(const __half* __restrict__ A, size_t lda,
                                          const __half* __restrict__ B, size_t ldb,
                                          int nkb, int tid, int wm, int wn,
                                          float c[4][8][4]) {
    extern __shared__ __half smh[];
    const uint32_t smb = smem_u32(smh);
    const int lane = tid & 31;
    constexpr uint32_t ABYTES = MR * PH * 2;
    const uint32_t aoff = ((wm * 64 + (lane & 15)) * PH + (lane >> 4) * 8) * 2u;
    const uint32_t boff = ((wn * 64 + (lane & 7) + ((lane >> 4) << 3)) * PH
                           + ((lane >> 3) & 1) * 8) * 2u;

    stage_cp<MR>(smb,          A, lda, tid);
    stage_cp<NR>(smb + ABYTES, B, ldb, tid);
    CP_COMMIT();
    if (nkb > 1) {
        stage_cp<MR>(smb + STAGEB,          A + BK, lda, tid);
        stage_cp<NR>(smb + STAGEB + ABYTES, B + BK, ldb, tid);
    }
    CP_COMMIT();

    for (int kb = 0; kb < nkb; kb++) {
        asm volatile("cp.async.wait_group 1;" ::: "memory");
        __syncthreads();
        if (kb + 2 < nkb) {
            const uint32_t st = ((kb + 2) % NSTAGE) * STAGEB;
            stage_cp<MR>(smb + st,          A + (size_t)(kb + 2) * BK, lda, tid);
            stage_cp<NR>(smb + st + ABYTES, B + (size_t)(kb + 2) * BK, ldb, tid);
        }
        CP_COMMIT();
        const uint32_t cs = (kb % NSTAGE) * STAGEB;
        compute_tile(smb + cs, smb + cs + ABYTES, aoff, boff, c);
    }
}

#define ZERO_ACC(c) do { \
    _Pragma("unroll") for (int m = 0; m < 4; m++) \
    _Pragma("unroll") for (int n = 0; n < 8; n++) \
    _Pragma("unroll") for (int i = 0; i < 4; i++) (c)[m][n][i] = 0.f; } while (0)

// ---------------- prep kernels ----------------
__global__ void roundx_kernel(const float* __restrict__ x) {
    size_t i = ((size_t)blockIdx.x * blockDim.x + threadIdx.x) * 4;
    float4 f = *(const float4*)(x + i);
    *(__half2*)(g_xh + i)     = __floats2half2_rn(f.x, f.y);
    *(__half2*)(g_xh + i + 2) = __floats2half2_rn(f.z, f.w);
}

__global__ void zerocs_kernel() {
    int i = blockIdx.x * blockDim.x + threadIdx.x;
    if (i < BT) g_colsum[i] = 0.f;
}

__global__ void transW_kernel(const float* __restrict__ Wq, const float* __restrict__ Wk,
                              const float* __restrict__ Wv) {
    __shared__ float t[32][33];
    const int sel = blockIdx.z;
    const float* W = (sel == 0) ? Wq : (sel == 1) ? Wk : Wv;
    const int k0 = blockIdx.x * 32, n0 = blockIdx.y * 32;
    const int tx = threadIdx.x, ty = threadIdx.y;
    #pragma unroll
    for (int j = 0; j < 4; j++)
        t[ty + 8*j][tx] = W[(size_t)(k0 + ty + 8*j) * HH + n0 + tx];
    __syncthreads();
    #pragma unroll
    for (int j = 0; j < 4; j++)
        g_Wth[(size_t)sel * HH * DD + (size_t)(n0 + ty + 8*j) * DD + k0 + tx] =
            __float2half_rn(t[tx][ty + 8*j]);
}

__global__ void scaleV_kernel() {
    __shared__ float t[32][33];
    const int b = blockIdx.z;
    const int k0 = blockIdx.x * 32, h0 = blockIdx.y * 32;
    const int tx = threadIdx.x, ty = threadIdx.y;
    #pragma unroll
    for (int j = 0; j < 4; j++) {
        int kk = k0 + ty + 8*j;
        float inv = 1.0f / g_colsum[(size_t)b * TT + kk];
        t[ty + 8*j][tx] = g_v[((size_t)b * TT + kk) * HH + h0 + tx] * inv;
    }
    __syncthreads();
    #pragma unroll
    for (int j = 0; j < 4; j++)
        g_Vth[((size_t)b * HH + h0 + ty + 8*j) * TT + k0 + tx] =
            __float2half_rn(t[tx][ty + 8*j]);
}

// ---------------- GEMM kernels (256 threads, warp tile 64x64) ----------------
// proj: block 256(M rows) x 128(N cols); warps 4(M) x 2(N)
__global__ __launch_bounds__(256, 1) void proj_tc(const float* __restrict__ bq,
                                                  const float* __restrict__ bk,
                                                  const float* __restrict__ bv) {
    const int tid = threadIdx.x;
    const int sel = blockIdx.y;
    const int row0 = blockIdx.x * 256;
    const int wid = tid >> 5, lane = tid & 31;
    const int wm = wid >> 1, wn = wid & 1;
    const int tr = lane >> 2, tc = lane & 3;

    float c[4][8][4];
    ZERO_ACC(c);
    gemm_main<256, 128>(g_xh + (size_t)row0 * DD, DD,
                        g_Wth + (size_t)sel * HH * DD, DD, DD / BK, tid, wm, wn, c);

    const float* bias = (sel == 0) ? bq : (sel == 1) ? bk : bv;
    const float sc = (sel == 0) ? 0.08838834764831845f : 1.0f;

    #pragma unroll
    for (int mt = 0; mt < 4; mt++) {
        const int row = row0 + wm * 64 + mt * 16 + tr;
        #pragma unroll
        for (int nt = 0; nt < 8; nt++) {
            const int col = wn * 64 + nt * 8 + tc * 2;
            const float b0 = bias[col], b1 = bias[col + 1];
            float lx = (c[mt][nt][0] + b0) * sc;
            float ly = (c[mt][nt][1] + b1) * sc;
            float hx = (c[mt][nt][2] + b0) * sc;
            float hy = (c[mt][nt][3] + b1) * sc;
            if (sel != 2) {
                __half* dst = (sel == 0) ? g_qh : g_kh;
                *(__half2*)(dst + (size_t)row * HH + col)       = __floats2half2_rn(lx, ly);
                *(__half2*)(dst + (size_t)(row + 8) * HH + col) = __floats2half2_rn(hx, hy);
            } else {
                *(float2*)(g_v + (size_t)row * HH + col)       = make_float2(lx, ly);
                *(float2*)(g_v + (size_t)(row + 8) * HH + col) = make_float2(hx, hy);
            }
        }
    }
}

// scores: block 128(q) x 256(k); warps 2(M) x 4(N). Also zero-fills E above diag
// within the covered 256-wide k tile, and accumulates colsum.
__global__ __launch_bounds__(256, 1) void scores_tc() {
    const int kt2 = blockIdx.x, qt = blockIdx.y, b = blockIdx.z;
    if (qt < 2 * kt2) return;
    const int tid = threadIdx.x;
    const int q0 = qt * 128, k0 = kt2 * 256;
    const int wid = tid >> 5, lane = tid & 31;
    const int wm = wid & 1, wn = wid >> 1;
    const int tr = lane >> 2, tc = lane & 3;

    float c[4][8][4];
    ZERO_ACC(c);
    gemm_main<128, 256>(g_qh + ((size_t)b * TT + q0) * HH, HH,
                        g_kh + ((size_t)b * TT + k0) * HH, HH, HH / BK, tid, wm, wn, c);

    __shared__ float red[256];
    __syncthreads();
    red[tid] = 0.f;
    __syncthreads();

    #pragma unroll
    for (int nt = 0; nt < 8; nt++) {
        const int kcol = wn * 64 + nt * 8 + tc * 2;
        const int k = k0 + kcol;
        float cs0 = 0.f, cs1 = 0.f;
        #pragma unroll
        for (int mt = 0; mt < 4; mt++) {
            const int q = q0 + wm * 64 + mt * 16 + tr;
            float lx = (q     >= k    ) ? __expf(c[mt][nt][0]) : 0.f;
            float ly = (q     >= k + 1) ? __expf(c[mt][nt][1]) : 0.f;
            float hx = (q + 8 >= k    ) ? __expf(c[mt][nt][2]) : 0.f;
            float hy = (q + 8 >= k + 1) ? __expf(c[mt][nt][3]) : 0.f;
            *(__half2*)(g_Eh + ((size_t)b * TT + q) * TT + k)     = __floats2half2_rn(lx, ly);
            *(__half2*)(g_Eh + ((size_t)b * TT + q + 8) * TT + k) = __floats2half2_rn(hx, hy);
            cs0 += lx + hx;
            cs1 += ly + hy;
        }
        atomicAdd(&red[kcol],     cs0);
        atomicAdd(&red[kcol + 1], cs1);
    }
    __syncthreads();
    atomicAdd(&g_colsum[(size_t)b * TT + k0 + tid], red[tid]);
}

// pv: block 256(q rows) x 128(H); warps 4(M) x 2(N). nk = (qt2+1)*256.
__global__ __launch_bounds__(256, 1) void pv_tc(float* __restrict__ out) {
    const int tid = threadIdx.x;
    const int qt2 = blockIdx.x, b = blockIdx.y;
    const int q0 = qt2 * 256;
    const int wid = tid >> 5, lane = tid & 31;
    const int wm = wid >> 1, wn = wid & 1;
    const int tr = lane >> 2, tc = lane & 3;

    float c[4][8][4];
    ZERO_ACC(c);
    gemm_main<256, 128>(g_Eh + ((size_t)b * TT + q0) * TT, TT,
                        g_Vth + (size_t)b * HH * TT, TT, (qt2 + 1) * 4, tid, wm, wn, c);

    #pragma unroll
    for (int mt = 0; mt < 4; mt++) {
        const int q = q0 + wm * 64 + mt * 16 + tr;
        #pragma unroll
        for (int nt = 0; nt < 8; nt++) {
            const int col = wn * 64 + nt * 8 + tc * 2;
            *(float2*)(out + ((size_t)b * TT + q) * HH + col) =
                make_float2(c[mt][nt][0], c[mt][nt][1]);
            *(float2*)(out + ((size_t)b * TT + q + 8) * HH + col) =
                make_float2(c[mt][nt][2], c[mt][nt][3]);
        }
    }
}

// ---------------- launch ----------------
extern "C" void kernel_launch(void* const* d_in, const int* in_sizes, int n_in,
                              void* d_out, int out_size) {
    const float* x  = (const float*)d_in[0];
    const float* Wk = (const float*)d_in[1];
    const float* bk = (const float*)d_in[2];
    const float* Wq = (const float*)d_in[3];
    const float* bq = (const float*)d_in[4];
    const float* Wv = (const float*)d_in[5];
    const float* bv = (const float*)d_in[6];
    float* out = (float*)d_out;

    cudaFuncSetAttribute(proj_tc,   cudaFuncAttributeMaxDynamicSharedMemorySize, GEMM_SMEM);
    cudaFuncSetAttribute(scores_tc, cudaFuncAttributeMaxDynamicSharedMemorySize, GEMM_SMEM);
    cudaFuncSetAttribute(pv_tc,     cudaFuncAttributeMaxDynamicSharedMemorySize, GEMM_SMEM);

    roundx_kernel<<<(size_t)BT * DD / 1024, 256>>>(x);
    zerocs_kernel<<<(BT + 255) / 256, 256>>>();
    transW_kernel<<<dim3(DD/32, HH/32, 3), dim3(32, 8)>>>(Wq, Wk, Wv);
    proj_tc<<<dim3(BT/256, 3), 256, GEMM_SMEM>>>(bq, bk, bv);
    scores_tc<<<dim3(TT/256, TT/128, BB), 256, GEMM_SMEM>>>();
    scaleV_kernel<<<dim3(TT/32, HH/32, BB), dim3(32, 8)>>>();
    pv_tc<<<dim3(TT/256, BB), 256, GEMM_SMEM>>>(out);
}

// round 9
// speedup vs baseline: 1.2007x; 1.2007x over previous
#include <cuda_runtime.h>
#include <cuda_fp16.h>
#include <cstdint>

#define BB 16
#define TT 2048
#define DD 1024
#define HH 128
#define BT (BB*TT)

// ---------------- device scratch (allocation-free rule) ----------------
__device__ __align__(128) __half g_xh[(size_t)BT*DD];      // half copy of x
__device__ __align__(128) __half g_qh[(size_t)BT*HH];      // half, pre-scaled
__device__ __align__(128) __half g_kh[(size_t)BT*HH];
__device__ __align__(128) float  g_v [(size_t)BT*HH];      // fp32 (scaled later)
__device__ __align__(128) __half g_Wth[3*(size_t)HH*DD];   // [sel][n][k]
__device__ __align__(128) __half g_Vth[(size_t)BB*HH*TT];  // [b][h][k] = v/colsum
__device__ __align__(128) float  g_colsum[BT];
__device__ __align__(128) __half g_Eh[(size_t)BB*TT*TT];   // exp(masked S)

// ---------------- helpers ----------------
__device__ __forceinline__ uint32_t smem_u32(const void* p) {
    uint32_t a;
    asm("{ .reg .u64 t; cvta.to.shared.u64 t, %1; cvt.u32.u64 %0, t; }" : "=r"(a) : "l"(p));
    return a;
}
__device__ __forceinline__ void ldsm4(uint32_t& r0, uint32_t& r1, uint32_t& r2, uint32_t& r3,
                                      uint32_t addr) {
    asm volatile("ldmatrix.sync.aligned.m8n8.x4.shared.b16 {%0,%1,%2,%3}, [%4];"
                 : "=r"(r0), "=r"(r1), "=r"(r2), "=r"(r3) : "r"(addr));
}
__device__ __forceinline__ void mma16(float* c, const uint32_t* a, const uint32_t* b) {
    asm volatile(
        "mma.sync.aligned.m16n8k16.row.col.f32.f16.f16.f32 "
        "{%0,%1,%2,%3}, {%4,%5,%6,%7}, {%8,%9}, {%0,%1,%2,%3};"
        : "+f"(c[0]), "+f"(c[1]), "+f"(c[2]), "+f"(c[3])
        : "r"(a[0]), "r"(a[1]), "r"(a[2]), "r"(a[3]), "r"(b[0]), "r"(b[1]));
}

#define BK 64                    // k-slab (halves)
#define PH 72                    // halves per smem row (144B): ldmatrix conflict-free
#define NSTAGE 3
#define STAGEB ((256 + 128) * PH * 2)        // 55296 B (MR+NR = 384 rows)
#define GEMM_SMEM (NSTAGE * STAGEB)          // 165888 B

// cp.async 16B stage of a ROWSx64-half chunk (row stride ld halves), 512 threads
template<int ROWS>
__device__ __forceinline__ void stage_cp(uint32_t s, const __half* __restrict__ g,
                                         size_t ld, int tid) {
    #pragma unroll
    for (int i = 0; i < ROWS / 64; i++) {
        int idx = tid + i * 512;
        int r = idx >> 3, c8 = idx & 7;
        uint32_t dst = s + (uint32_t)(r * PH + c8 * 8) * 2u;
        const __half* src = g + (size_t)r * ld + c8 * 8;
        asm volatile("cp.async.cg.shared.global [%0], [%1], 16;" :: "r"(dst), "l"(src));
    }
}
#define CP_COMMIT() asm volatile("cp.async.commit_group;" ::: "memory")

// warp tile 64(M) x 32(N). One BK=64 slab = four k16 steps.
__device__ __forceinline__ void compute_tile(uint32_t sA, uint32_t sB,
                                             uint32_t aoff, uint32_t boff,
                                             float c[4][4][4]) {
    #pragma unroll
    for (int ks = 0; ks < 4; ks++) {
        uint32_t a[4][4], b[4][2];
        #pragma unroll
        for (int mt = 0; mt < 4; mt++)
            ldsm4(a[mt][0], a[mt][1], a[mt][2], a[mt][3],
                  sA + aoff + mt * (16 * PH * 2) + ks * 32);
        #pragma unroll
        for (int np = 0; np < 2; np++)
            ldsm4(b[2*np][0], b[2*np][1], b[2*np+1][0], b[2*np+1][1],
                  sB + boff + np * (16 * PH * 2) + ks * 32);
        #pragma unroll
        for (int mt = 0; mt < 4; mt++)
            #pragma unroll
            for (int nt = 0; nt < 4; nt++)
                mma16(c[mt][nt], a[mt], b[nt]);
    }
}

// block GEMM: C[MRxNR] = A[MRxK] * B[NRxK]^T, 512 threads, 3 cp.async stages
template<int MR, int NR>
__device__ __forceinline__ void gemm_main(const __half* __restrict__ A, size_t lda,
                                          const __half* __restrict__ B, size_t ldb,
                                          int nkb, int tid, int wm, int wn,
                                          float c[4][4][4]) {
    extern __shared__ __half smh[];
    const uint32_t smb = smem_u32(smh);
    const int lane = tid & 31;
    constexpr uint32_t ABYTES = MR * PH * 2;
    const uint32_t aoff = ((wm * 64 + (lane & 15)) * PH + (lane >> 4) * 8) * 2u;
    const uint32_t boff = ((wn * 32 + (lane & 7) + ((lane >> 4) << 3)) * PH
                           + ((lane >> 3) & 1) * 8) * 2u;

    stage_cp<MR>(smb,          A, lda, tid);
    stage_cp<NR>(smb + ABYTES, B, ldb, tid);
    CP_COMMIT();
    if (nkb > 1) {
        stage_cp<MR>(smb + STAGEB,          A + BK, lda, tid);
        stage_cp<NR>(smb + STAGEB + ABYTES, B + BK, ldb, tid);
    }
    CP_COMMIT();

    for (int kb = 0; kb < nkb; kb++) {
        asm volatile("cp.async.wait_group 1;" ::: "memory");
        __syncthreads();
        if (kb + 2 < nkb) {
            const uint32_t st = ((kb + 2) % NSTAGE) * STAGEB;
            stage_cp<MR>(smb + st,          A + (size_t)(kb + 2) * BK, lda, tid);
            stage_cp<NR>(smb + st + ABYTES, B + (size_t)(kb + 2) * BK, ldb, tid);
        }
        CP_COMMIT();
        const uint32_t cs = (kb % NSTAGE) * STAGEB;
        compute_tile(smb + cs, smb + cs + ABYTES, aoff, boff, c);
    }
}

#define ZERO_ACC(c) do { \
    _Pragma("unroll") for (int m = 0; m < 4; m++) \
    _Pragma("unroll") for (int n = 0; n < 4; n++) \
    _Pragma("unroll") for (int i = 0; i < 4; i++) (c)[m][n][i] = 0.f; } while (0)

// ---------------- prep kernels ----------------
__global__ void roundx_kernel(const float* __restrict__ x) {
    size_t i = ((size_t)blockIdx.x * blockDim.x + threadIdx.x) * 4;
    float4 f = *(const float4*)(x + i);
    *(__half2*)(g_xh + i)     = __floats2half2_rn(f.x, f.y);
    *(__half2*)(g_xh + i + 2) = __floats2half2_rn(f.z, f.w);
}

__global__ void zerocs_kernel() {
    int i = blockIdx.x * blockDim.x + threadIdx.x;
    if (i < BT) g_colsum[i] = 0.f;
}

__global__ void zeroout_kernel(float* __restrict__ out) {
    size_t i = ((size_t)blockIdx.x * blockDim.x + threadIdx.x) * 4;
    *(float4*)(out + i) = make_float4(0.f, 0.f, 0.f, 0.f);
}

__global__ void transW_kernel(const float* __restrict__ Wq, const float* __restrict__ Wk,
                              const float* __restrict__ Wv) {
    __shared__ float t[32][33];
    const int sel = blockIdx.z;
    const float* W = (sel == 0) ? Wq : (sel == 1) ? Wk : Wv;
    const int k0 = blockIdx.x * 32, n0 = blockIdx.y * 32;
    const int tx = threadIdx.x, ty = threadIdx.y;
    #pragma unroll
    for (int j = 0; j < 4; j++)
        t[ty + 8*j][tx] = W[(size_t)(k0 + ty + 8*j) * HH + n0 + tx];
    __syncthreads();
    #pragma unroll
    for (int j = 0; j < 4; j++)
        g_Wth[(size_t)sel * HH * DD + (size_t)(n0 + ty + 8*j) * DD + k0 + tx] =
            __float2half_rn(t[tx][ty + 8*j]);
}

__global__ void scaleV_kernel() {
    __shared__ float t[32][33];
    const int b = blockIdx.z;
    const int k0 = blockIdx.x * 32, h0 = blockIdx.y * 32;
    const int tx = threadIdx.x, ty = threadIdx.y;
    #pragma unroll
    for (int j = 0; j < 4; j++) {
        int kk = k0 + ty + 8*j;
        float inv = 1.0f / g_colsum[(size_t)b * TT + kk];
        t[ty + 8*j][tx] = g_v[((size_t)b * TT + kk) * HH + h0 + tx] * inv;
    }
    __syncthreads();
    #pragma unroll
    for (int j = 0; j < 4; j++)
        g_Vth[((size_t)b * HH + h0 + ty + 8*j) * TT + k0 + tx] =
            __float2half_rn(t[tx][ty + 8*j]);
}

// ---------------- GEMM kernels (512 threads, warp tile 64x32) ----------------
// proj: block 256(M) x 128(N); 16 warps = 4(M) x 4(N)
__global__ __launch_bounds__(512, 1) void proj_tc(const float* __restrict__ bq,
                                                  const float* __restrict__ bk,
                                                  const float* __restrict__ bv) {
    const int tid = threadIdx.x;
    const int sel = blockIdx.y;
    const int row0 = blockIdx.x * 256;
    const int wid = tid >> 5, lane = tid & 31;
    const int wm = wid >> 2, wn = wid & 3;
    const int tr = lane >> 2, tc = lane & 3;

    float c[4][4][4];
    ZERO_ACC(c);
    gemm_main<256, 128>(g_xh + (size_t)row0 * DD, DD,
                        g_Wth + (size_t)sel * HH * DD, DD, DD / BK, tid, wm, wn, c);

    const float* bias = (sel == 0) ? bq : (sel == 1) ? bk : bv;
    const float sc = (sel == 0) ? 0.08838834764831845f : 1.0f;

    #pragma unroll
    for (int mt = 0; mt < 4; mt++) {
        const int row = row0 + wm * 64 + mt * 16 + tr;
        #pragma unroll
        for (int nt = 0; nt < 4; nt++) {
            const int col = wn * 32 + nt * 8 + tc * 2;
            const float b0 = bias[col], b1 = bias[col + 1];
            float lx = (c[mt][nt][0] + b0) * sc;
            float ly = (c[mt][nt][1] + b1) * sc;
            float hx = (c[mt][nt][2] + b0) * sc;
            float hy = (c[mt][nt][3] + b1) * sc;
            if (sel != 2) {
                __half* dst = (sel == 0) ? g_qh : g_kh;
                *(__half2*)(dst + (size_t)row * HH + col)       = __floats2half2_rn(lx, ly);
                *(__half2*)(dst + (size_t)(row + 8) * HH + col) = __floats2half2_rn(hx, hy);
            } else {
                *(float2*)(g_v + (size_t)row * HH + col)       = make_float2(lx, ly);
                *(float2*)(g_v + (size_t)(row + 8) * HH + col) = make_float2(hx, hy);
            }
        }
    }
}

// scores: block 128(q) x 256(k); 16 warps = 2(M) x 8(N). Writes E (zero above diag
// within covered tiles) and accumulates colsum via shfl + smem + global atomics.
__global__ __launch_bounds__(512, 1) void scores_tc() {
    const int kt2 = blockIdx.x, qt = blockIdx.y, b = blockIdx.z;
    if (qt < 2 * kt2) return;
    const int tid = threadIdx.x;
    const int q0 = qt * 128, k0 = kt2 * 256;
    const int wid = tid >> 5, lane = tid & 31;
    const int wm = wid & 1, wn = wid >> 1;
    const int tr = lane >> 2, tc = lane & 3;

    float c[4][4][4];
    ZERO_ACC(c);
    gemm_main<128, 256>(g_qh + ((size_t)b * TT + q0) * HH, HH,
                        g_kh + ((size_t)b * TT + k0) * HH, HH, HH / BK, tid, wm, wn, c);

    __shared__ float red[256];
    __syncthreads();
    if (tid < 256) red[tid] = 0.f;
    __syncthreads();

    #pragma unroll
    for (int nt = 0; nt < 4; nt++) {
        const int kcol = wn * 32 + nt * 8 + tc * 2;
        const int k = k0 + kcol;
        float cs0 = 0.f, cs1 = 0.f;
        #pragma unroll
        for (int mt = 0; mt < 4; mt++) {
            const int q = q0 + wm * 64 + mt * 16 + tr;
            float lx = (q     >= k    ) ? __expf(c[mt][nt][0]) : 0.f;
            float ly = (q     >= k + 1) ? __expf(c[mt][nt][1]) : 0.f;
            float hx = (q + 8 >= k    ) ? __expf(c[mt][nt][2]) : 0.f;
            float hy = (q + 8 >= k + 1) ? __expf(c[mt][nt][3]) : 0.f;
            *(__half2*)(g_Eh + ((size_t)b * TT + q) * TT + k)     = __floats2half2_rn(lx, ly);
            *(__half2*)(g_Eh + ((size_t)b * TT + q + 8) * TT + k) = __floats2half2_rn(hx, hy);
            cs0 += lx + hx;
            cs1 += ly + hy;
        }
        // reduce over tr lanes (same tc): lanes differ in bits 2..4
        #pragma unroll
        for (int m = 16; m >= 4; m >>= 1) {
            cs0 += __shfl_xor_sync(0xFFFFFFFF, cs0, m);
            cs1 += __shfl_xor_sync(0xFFFFFFFF, cs1, m);
        }
        if (lane < 4) {
            atomicAdd(&red[kcol],     cs0);
            atomicAdd(&red[kcol + 1], cs1);
        }
    }
    __syncthreads();
    if (tid < 256) atomicAdd(&g_colsum[(size_t)b * TT + k0 + tid], red[tid]);
}

// pv: block 256(q) x 128(H); 16 warps = 4(M) x 4(N). Split-k chunks of <=8 slabs,
// fp32 atomicAdd into zeroed out. Chunk map per qt2 (0..7): ceil((qt2+1)/2) chunks.
__global__ __launch_bounds__(512, 1) void pv_tc(float* __restrict__ out) {
    const int tid = threadIdx.x;
    const int b = blockIdx.y;
    const int wid = tid >> 5, lane = tid & 31;
    const int wm = wid >> 2, wn = wid & 3;
    const int tr = lane >> 2, tc = lane & 3;

    // decode blockIdx.x -> (qt2, chunk)
    int id = blockIdx.x, qt2 = 0, ch = 0;
    #pragma unroll
    for (int q = 0; q < 8; q++) {
        int nch = (q + 2) >> 1;          // ceil((q+1)/2)
        if (id < nch) { qt2 = q; ch = id; break; }
        id -= nch;
    }
    const int q0 = qt2 * 256;
    const int nkb_tot = (qt2 + 1) * 4;   // BK=64 slabs over k in [0,(qt2+1)*256)
    const int kb0 = ch * 8;
    const int nkb = min(8, nkb_tot - kb0);

    float c[4][4][4];
    ZERO_ACC(c);
    gemm_main<256, 128>(g_Eh + ((size_t)b * TT + q0) * TT + (size_t)kb0 * BK, TT,
                        g_Vth + (size_t)b * HH * TT + (size_t)kb0 * BK, TT,
                        nkb, tid, wm, wn, c);

    #pragma unroll
    for (int mt = 0; mt < 4; mt++) {
        const int q = q0 + wm * 64 + mt * 16 + tr;
        #pragma unroll
        for (int nt = 0; nt < 4; nt++) {
            const int col = wn * 32 + nt * 8 + tc * 2;
            float* p0 = out + ((size_t)b * TT + q) * HH + col;
            float* p1 = out + ((size_t)b * TT + q + 8) * HH + col;
            atomicAdd(p0,     c[mt][nt][0]);
            atomicAdd(p0 + 1, c[mt][nt][1]);
            atomicAdd(p1,     c[mt][nt][2]);
            atomicAdd(p1 + 1, c[mt][nt][3]);
        }
    }
}

// ---------------- launch ----------------
extern "C" void kernel_launch(void* const* d_in, const int* in_sizes, int n_in,
                              void* d_out, int out_size) {
    const float* x  = (const float*)d_in[0];
    const float* Wk = (const float*)d_in[1];
    const float* bk = (const float*)d_in[2];
    const float* Wq = (const float*)d_in[3];
    const float* bq = (const float*)d_in[4];
    const float* Wv = (const float*)d_in[5];
    const float* bv = (const float*)d_in[6];
    float* out = (float*)d_out;

    cudaFuncSetAttribute(proj_tc,   cudaFuncAttributeMaxDynamicSharedMemorySize, GEMM_SMEM);
    cudaFuncSetAttribute(scores_tc, cudaFuncAttributeMaxDynamicSharedMemorySize, GEMM_SMEM);
    cudaFuncSetAttribute(pv_tc,     cudaFuncAttributeMaxDynamicSharedMemorySize, GEMM_SMEM);

    roundx_kernel<<<(size_t)BT * DD / 1024, 256>>>(x);
    zerocs_kernel<<<(BT + 255) / 256, 256>>>();
    zeroout_kernel<<<(size_t)BT * HH / 1024, 256>>>(out);
    transW_kernel<<<dim3(DD/32, HH/32, 3), dim3(32, 8)>>>(Wq, Wk, Wv);
    proj_tc<<<dim3(BT/256, 3), 512, GEMM_SMEM>>>(bq, bk, bv);
    scores_tc<<<dim3(TT/256, TT/128, BB), 512, GEMM_SMEM>>>();
    scaleV_kernel<<<dim3(TT/32, HH/32, BB), dim3(32, 8)>>>();
    pv_tc<<<dim3(20, BB), 512, GEMM_SMEM>>>(out);
}

// round 10
// speedup vs baseline: 1.3097x; 1.0908x over previous
#include <cuda_runtime.h>
#include <cuda_fp16.h>
#include <cstdint>

#define BB 16
#define TT 2048
#define DD 1024
#define HH 128
#define BT (BB*TT)

// ---------------- device scratch (allocation-free rule) ----------------
__device__ __align__(128) __half g_xh[(size_t)BT*DD];      // half copy of x
__device__ __align__(128) __half g_qh[(size_t)BT*HH];      // half, pre-scaled
__device__ __align__(128) __half g_kh[(size_t)BT*HH];
__device__ __align__(128) float  g_v [(size_t)BT*HH];      // fp32 (scaled later)
__device__ __align__(128) __half g_Wth[3*(size_t)HH*DD];   // [sel][n][k]
__device__ __align__(128) __half g_Vth[(size_t)BB*HH*TT];  // [b][h][k] = v/colsum
__device__ __align__(128) float  g_colsum[BT];
__device__ __align__(128) __half g_Eh[(size_t)BB*TT*TT];   // exp(masked S)

// ---------------- helpers ----------------
__device__ __forceinline__ uint32_t smem_u32(const void* p) {
    uint32_t a;
    asm("{ .reg .u64 t; cvta.to.shared.u64 t, %1; cvt.u32.u64 %0, t; }" : "=r"(a) : "l"(p));
    return a;
}
__device__ __forceinline__ void ldsm4(uint32_t& r0, uint32_t& r1, uint32_t& r2, uint32_t& r3,
                                      uint32_t addr) {
    asm volatile("ldmatrix.sync.aligned.m8n8.x4.shared.b16 {%0,%1,%2,%3}, [%4];"
                 : "=r"(r0), "=r"(r1), "=r"(r2), "=r"(r3) : "r"(addr));
}
__device__ __forceinline__ void mma16(float* c, const uint32_t* a, const uint32_t* b) {
    asm volatile(
        "mma.sync.aligned.m16n8k16.row.col.f32.f16.f16.f32 "
        "{%0,%1,%2,%3}, {%4,%5,%6,%7}, {%8,%9}, {%0,%1,%2,%3};"
        : "+f"(c[0]), "+f"(c[1]), "+f"(c[2]), "+f"(c[3])
        : "r"(a[0]), "r"(a[1]), "r"(a[2]), "r"(a[3]), "r"(b[0]), "r"(b[1]));
}

#define BK 64                    // k-slab (halves) for multistage GEMMs
#define PH 72                    // halves per smem row (BK=64 +8): ldmatrix conflict-free
#define TILEH (128*PH)
#define TILEB (TILEH*2)          // 18432 B per 128x64 tile
#define NSTAGE 3
#define GEMM_SMEM (NSTAGE*2*TILEB)   // 110592 B (2 CTAs/SM)

// scores: full-K single-stage tiles (128 x 128 halves, PH2 = 136)
#define PH2 136
#define TILE2B (128*PH2*2)       // 34816 B
#define SC_SMEM (2*TILE2B)       // 69632 B (2 CTAs/SM)

#define CP_COMMIT() asm volatile("cp.async.commit_group;" ::: "memory")

// cp.async 16B stage of a 128x64-half chunk (row stride ld halves), 256 threads
__device__ __forceinline__ void stage_cp(uint32_t s, const __half* __restrict__ g,
                                         size_t ld, int tid) {
    #pragma unroll
    for (int i = 0; i < 4; i++) {
        int idx = tid + i * 256;
        int r = idx >> 3, c8 = idx & 7;
        uint32_t dst = s + (uint32_t)(r * PH + c8 * 8) * 2u;
        const __half* src = g + (size_t)r * ld + c8 * 8;
        asm volatile("cp.async.cg.shared.global [%0], [%1], 16;" :: "r"(dst), "l"(src));
    }
}

// cp.async 16B stage of a full 128x128-half tile (PH2 pitch), 256 threads
__device__ __forceinline__ void stage_cp_full(uint32_t s, const __half* __restrict__ g,
                                              size_t ld, int tid) {
    #pragma unroll
    for (int i = 0; i < 8; i++) {
        int idx = tid + i * 256;
        int r = idx >> 4, c8 = idx & 15;
        uint32_t dst = s + (uint32_t)(r * PH2 + c8 * 8) * 2u;
        const __half* src = g + (size_t)r * ld + c8 * 8;
        asm volatile("cp.async.cg.shared.global [%0], [%1], 16;" :: "r"(dst), "l"(src));
    }
}

// warp tile 64(M) x 32(N). One BK=64 slab = four k16 steps. (PH pitch)
__device__ __forceinline__ void compute_tile(uint32_t sA, uint32_t sB,
                                             uint32_t aoff, uint32_t boff,
                                             float c[4][4][4]) {
    #pragma unroll
    for (int ks = 0; ks < 4; ks++) {
        uint32_t a[4][4], b[4][2];
        #pragma unroll
        for (int mt = 0; mt < 4; mt++)
            ldsm4(a[mt][0], a[mt][1], a[mt][2], a[mt][3],
                  sA + aoff + mt * (16 * PH * 2) + ks * 32);
        #pragma unroll
        for (int np = 0; np < 2; np++)
            ldsm4(b[2*np][0], b[2*np][1], b[2*np+1][0], b[2*np+1][1],
                  sB + boff + np * (16 * PH * 2) + ks * 32);
        #pragma unroll
        for (int mt = 0; mt < 4; mt++)
            #pragma unroll
            for (int nt = 0; nt < 4; nt++)
                mma16(c[mt][nt], a[mt], b[nt]);
    }
}

// block GEMM: C[128x128] = A[128xK] * B[128xK]^T, 256 threads, 3 cp.async stages
__device__ __forceinline__ void gemm_main(const __half* __restrict__ A, size_t lda,
                                          const __half* __restrict__ B, size_t ldb,
                                          int nkb, int tid, float c[4][4][4]) {
    extern __shared__ __half smh[];
    const uint32_t smb = smem_u32(smh);
    const int wid = tid >> 5, lane = tid & 31;
    const int wm = wid & 1, wn = wid >> 1;
    const uint32_t aoff = ((wm * 64 + (lane & 15)) * PH + (lane >> 4) * 8) * 2u;
    const uint32_t boff = ((wn * 32 + (lane & 7) + ((lane >> 4) << 3)) * PH
                           + ((lane >> 3) & 1) * 8) * 2u;

    __syncthreads();   // protect smem from previous GEMM in the same block

    stage_cp(smb,         A, lda, tid);
    stage_cp(smb + TILEB, B, ldb, tid);
    CP_COMMIT();
    if (nkb > 1) {
        stage_cp(smb + 2 * TILEB, A + BK, lda, tid);
        stage_cp(smb + 3 * TILEB, B + BK, ldb, tid);
    }
    CP_COMMIT();

    for (int kb = 0; kb < nkb; kb++) {
        asm volatile("cp.async.wait_group 1;" ::: "memory");
        __syncthreads();
        if (kb + 2 < nkb) {
            const int st = (kb + 2) % NSTAGE;
            stage_cp(smb + (2 * st) * TILEB,     A + (size_t)(kb + 2) * BK, lda, tid);
            stage_cp(smb + (2 * st + 1) * TILEB, B + (size_t)(kb + 2) * BK, ldb, tid);
        }
        CP_COMMIT();
        const int cs = kb % NSTAGE;
        compute_tile(smb + (2 * cs) * TILEB, smb + (2 * cs + 1) * TILEB, aoff, boff, c);
    }
}

#define ZERO_ACC(c) do { \
    _Pragma("unroll") for (int m = 0; m < 4; m++) \
    _Pragma("unroll") for (int n = 0; n < 4; n++) \
    _Pragma("unroll") for (int i = 0; i < 4; i++) (c)[m][n][i] = 0.f; } while (0)

// ---------------- prep kernels ----------------
__global__ void roundx_kernel(const float* __restrict__ x) {
    size_t i = ((size_t)blockIdx.x * blockDim.x + threadIdx.x) * 4;
    float4 f = *(const float4*)(x + i);
    *(__half2*)(g_xh + i)     = __floats2half2_rn(f.x, f.y);
    *(__half2*)(g_xh + i + 2) = __floats2half2_rn(f.z, f.w);
}

__global__ void zerocs_kernel() {
    int i = blockIdx.x * blockDim.x + threadIdx.x;
    if (i < BT) g_colsum[i] = 0.f;
}

__global__ void zeroout_kernel(float* __restrict__ out) {
    size_t i = ((size_t)blockIdx.x * blockDim.x + threadIdx.x) * 4;
    *(float4*)(out + i) = make_float4(0.f, 0.f, 0.f, 0.f);
}

__global__ void transW_kernel(const float* __restrict__ Wq, const float* __restrict__ Wk,
                              const float* __restrict__ Wv) {
    __shared__ float t[32][33];
    const int sel = blockIdx.z;
    const float* W = (sel == 0) ? Wq : (sel == 1) ? Wk : Wv;
    const int k0 = blockIdx.x * 32, n0 = blockIdx.y * 32;
    const int tx = threadIdx.x, ty = threadIdx.y;
    #pragma unroll
    for (int j = 0; j < 4; j++)
        t[ty + 8*j][tx] = W[(size_t)(k0 + ty + 8*j) * HH + n0 + tx];
    __syncthreads();
    #pragma unroll
    for (int j = 0; j < 4; j++)
        g_Wth[(size_t)sel * HH * DD + (size_t)(n0 + ty + 8*j) * DD + k0 + tx] =
            __float2half_rn(t[tx][ty + 8*j]);
}

__global__ void scaleV_kernel() {
    __shared__ float t[32][33];
    const int b = blockIdx.z;
    const int k0 = blockIdx.x * 32, h0 = blockIdx.y * 32;
    const int tx = threadIdx.x, ty = threadIdx.y;
    #pragma unroll
    for (int j = 0; j < 4; j++) {
        int kk = k0 + ty + 8*j;
        float inv = 1.0f / g_colsum[(size_t)b * TT + kk];
        t[ty + 8*j][tx] = g_v[((size_t)b * TT + kk) * HH + h0 + tx] * inv;
    }
    __syncthreads();
    #pragma unroll
    for (int j = 0; j < 4; j++)
        g_Vth[((size_t)b * HH + h0 + ty + 8*j) * TT + k0 + tx] =
            __float2half_rn(t[tx][ty + 8*j]);
}

// ---------------- proj (R7 config: 256 thr, 128x128, BK=64, 3 stages) ----------------
__global__ __launch_bounds__(256, 2) void proj_tc(const float* __restrict__ bq,
                                                  const float* __restrict__ bk,
                                                  const float* __restrict__ bv) {
    const int tid = threadIdx.x;
    const int sel = blockIdx.y;
    const int row0 = blockIdx.x * 128;

    float c[4][4][4];
    ZERO_ACC(c);
    gemm_main(g_xh + (size_t)row0 * DD, DD,
              g_Wth + (size_t)sel * HH * DD, DD, DD / BK, tid, c);

    const int wid = tid >> 5, lane = tid & 31;
    const int wm = wid & 1, wn = wid >> 1;
    const int tr = lane >> 2, tc = lane & 3;
    const float* bias = (sel == 0) ? bq : (sel == 1) ? bk : bv;
    const float sc = (sel == 0) ? 0.08838834764831845f : 1.0f;

    #pragma unroll
    for (int mt = 0; mt < 4; mt++) {
        const int row = row0 + wm * 64 + mt * 16 + tr;
        #pragma unroll
        for (int nt = 0; nt < 4; nt++) {
            const int col = wn * 32 + nt * 8 + tc * 2;
            const float b0 = bias[col], b1 = bias[col + 1];
            float lx = (c[mt][nt][0] + b0) * sc;
            float ly = (c[mt][nt][1] + b1) * sc;
            float hx = (c[mt][nt][2] + b0) * sc;
            float hy = (c[mt][nt][3] + b1) * sc;
            if (sel != 2) {
                __half* dst = (sel == 0) ? g_qh : g_kh;
                *(__half2*)(dst + (size_t)row * HH + col)       = __floats2half2_rn(lx, ly);
                *(__half2*)(dst + (size_t)(row + 8) * HH + col) = __floats2half2_rn(hx, hy);
            } else {
                *(float2*)(g_v + (size_t)row * HH + col)       = make_float2(lx, ly);
                *(float2*)(g_v + (size_t)(row + 8) * HH + col) = make_float2(hx, hy);
            }
        }
    }
}

// ---------------- scores: full-K single-stage, zero mainloop barriers ----------------
__global__ __launch_bounds__(256, 2) void scores_tc() {
    const int kt = blockIdx.x, qt = blockIdx.y, b = blockIdx.z;
    if (qt < kt) return;
    extern __shared__ __half smh[];
    const uint32_t smb = smem_u32(smh);
    const int tid = threadIdx.x;
    const int q0 = qt * 128, k0 = kt * 128;
    const int wid = tid >> 5, lane = tid & 31;
    const int wm = wid & 1, wn = wid >> 1;
    const int tr = lane >> 2, tc = lane & 3;

    stage_cp_full(smb,          g_qh + ((size_t)b * TT + q0) * HH, HH, tid);
    stage_cp_full(smb + TILE2B, g_kh + ((size_t)b * TT + k0) * HH, HH, tid);
    CP_COMMIT();

    float c[4][4][4];
    ZERO_ACC(c);

    const uint32_t aoff = ((wm * 64 + (lane & 15)) * PH2 + (lane >> 4) * 8) * 2u;
    const uint32_t boff = ((wn * 32 + (lane & 7) + ((lane >> 4) << 3)) * PH2
                           + ((lane >> 3) & 1) * 8) * 2u;

    asm volatile("cp.async.wait_group 0;" ::: "memory");
    __syncthreads();

    #pragma unroll
    for (int ks = 0; ks < 8; ks++) {
        uint32_t a[4][4], bfr[4][2];
        #pragma unroll
        for (int mt = 0; mt < 4; mt++)
            ldsm4(a[mt][0], a[mt][1], a[mt][2], a[mt][3],
                  smb + aoff + mt * (16 * PH2 * 2) + ks * 32);
        #pragma unroll
        for (int np = 0; np < 2; np++)
            ldsm4(bfr[2*np][0], bfr[2*np][1], bfr[2*np+1][0], bfr[2*np+1][1],
                  smb + TILE2B + boff + np * (16 * PH2 * 2) + ks * 32);
        #pragma unroll
        for (int mt = 0; mt < 4; mt++)
            #pragma unroll
            for (int nt = 0; nt < 4; nt++)
                mma16(c[mt][nt], a[mt], bfr[nt]);
    }

    __shared__ float red[128];
    __syncthreads();
    if (tid < 128) red[tid] = 0.f;
    __syncthreads();

    #pragma unroll
    for (int nt = 0; nt < 4; nt++) {
        const int kcol = wn * 32 + nt * 8 + tc * 2;
        const int k = k0 + kcol;
        float cs0 = 0.f, cs1 = 0.f;
        #pragma unroll
        for (int mt = 0; mt < 4; mt++) {
            const int q = q0 + wm * 64 + mt * 16 + tr;
            float lx = (q     >= k    ) ? __expf(c[mt][nt][0]) : 0.f;
            float ly = (q     >= k + 1) ? __expf(c[mt][nt][1]) : 0.f;
            float hx = (q + 8 >= k    ) ? __expf(c[mt][nt][2]) : 0.f;
            float hy = (q + 8 >= k + 1) ? __expf(c[mt][nt][3]) : 0.f;
            *(__half2*)(g_Eh + ((size_t)b * TT + q) * TT + k)     = __floats2half2_rn(lx, ly);
            *(__half2*)(g_Eh + ((size_t)b * TT + q + 8) * TT + k) = __floats2half2_rn(hx, hy);
            cs0 += lx + hx;
            cs1 += ly + hy;
        }
        #pragma unroll
        for (int m = 16; m >= 4; m >>= 1) {
            cs0 += __shfl_xor_sync(0xFFFFFFFF, cs0, m);
            cs1 += __shfl_xor_sync(0xFFFFFFFF, cs1, m);
        }
        if (lane < 4) {
            atomicAdd(&red[kcol],     cs0);
            atomicAdd(&red[kcol + 1], cs1);
        }
    }
    __syncthreads();
    if (tid < 128) atomicAdd(&g_colsum[(size_t)b * TT + k0 + tid], red[tid]);
}

// ---------------- pv: split-k, 256-thr 128x128 blocks, chunks <= 8 slabs ----------------
// per qt (0..15): nkb_tot=(qt+1)*2 slabs; nch=ceil(nkb_tot/8); sum over qt = 40.
__global__ __launch_bounds__(256, 2) void pv_tc(float* __restrict__ out) {
    const int tid = threadIdx.x;
    const int b = blockIdx.y;
    const int wid = tid >> 5, lane = tid & 31;
    const int wm = wid & 1, wn = wid >> 1;
    const int tr = lane >> 2, tc = lane & 3;

    int id = blockIdx.x, qt = 0, ch = 0;
    #pragma unroll
    for (int q = 0; q < 16; q++) {
        int nch = (2 * (q + 1) + 7) >> 3;
        if (id < nch) { qt = q; ch = id; break; }
        id -= nch;
    }
    const int q0 = qt * 128;
    const int nkb_tot = (qt + 1) * 2;
    const int kb0 = ch * 8;
    const int nkb = min(8, nkb_tot - kb0);

    float c[4][4][4];
    ZERO_ACC(c);
    gemm_main(g_Eh + ((size_t)b * TT + q0) * TT + (size_t)kb0 * BK, TT,
              g_Vth + (size_t)b * HH * TT + (size_t)kb0 * BK, TT, nkb, tid, c);

    #pragma unroll
    for (int mt = 0; mt < 4; mt++) {
        const int q = q0 + wm * 64 + mt * 16 + tr;
        #pragma unroll
        for (int nt = 0; nt < 4; nt++) {
            const int col = wn * 32 + nt * 8 + tc * 2;
            float* p0 = out + ((size_t)b * TT + q) * HH + col;
            float* p1 = out + ((size_t)b * TT + q + 8) * HH + col;
            atomicAdd(p0,     c[mt][nt][0]);
            atomicAdd(p0 + 1, c[mt][nt][1]);
            atomicAdd(p1,     c[mt][nt][2]);
            atomicAdd(p1 + 1, c[mt][nt][3]);
        }
    }
}

// ---------------- launch ----------------
extern "C" void kernel_launch(void* const* d_in, const int* in_sizes, int n_in,
                              void* d_out, int out_size) {
    const float* x  = (const float*)d_in[0];
    const float* Wk = (const float*)d_in[1];
    const float* bk = (const float*)d_in[2];
    const float* Wq = (const float*)d_in[3];
    const float* bq = (const float*)d_in[4];
    const float* Wv = (const float*)d_in[5];
    const float* bv = (const float*)d_in[6];
    float* out = (float*)d_out;

    cudaFuncSetAttribute(proj_tc,   cudaFuncAttributeMaxDynamicSharedMemorySize, GEMM_SMEM);
    cudaFuncSetAttribute(scores_tc, cudaFuncAttributeMaxDynamicSharedMemorySize, SC_SMEM);
    cudaFuncSetAttribute(pv_tc,     cudaFuncAttributeMaxDynamicSharedMemorySize, GEMM_SMEM);

    roundx_kernel<<<(size_t)BT * DD / 1024, 256>>>(x);
    zerocs_kernel<<<(BT + 255) / 256, 256>>>();
    zeroout_kernel<<<(size_t)BT * HH / 1024, 256>>>(out);
    transW_kernel<<<dim3(DD/32, HH/32, 3), dim3(32, 8)>>>(Wq, Wk, Wv);
    proj_tc<<<dim3(BT/128, 3), 256, GEMM_SMEM>>>(bq, bk, bv);
    scores_tc<<<dim3(TT/128, TT/128, BB), 256, SC_SMEM>>>();
    scaleV_kernel<<<dim3(TT/32, HH/32, BB), dim3(32, 8)>>>();
    pv_tc<<<dim3(40, BB), 256, GEMM_SMEM>>>(out);
}